// round 9
// baseline (speedup 1.0000x reference)
#include <cuda_runtime.h>
#include <cuda_bf16.h>
#include <cstdint>

#define MM 9
#define DD 128
#define NMAX 8192

// ---------------- global scratch (static, no dynamic alloc) ----------------
static __device__ __align__(128) float g_g[NMAX * MM * DD];

// ---------------- helpers ---------------------------------------------------
__device__ __forceinline__ uint32_t bswz(int row, int q) {
    int c = q >> 1;
    int cs = (c & 8) | ((c & 7) ^ (row & 7));
    return (uint32_t)(row * 256 + cs * 16 + (q & 1) * 8);
}
__device__ __forceinline__ uint32_t lmaddr(uint32_t base, int row, int chunk) {
    int cs = (chunk & 8) | ((chunk & 7) ^ (row & 7));
    return base + (uint32_t)(row * 256 + cs * 16);
}
__device__ __forceinline__ uint32_t smem_u32(const void* p) {
    uint32_t a;
    asm("{ .reg .u64 t; cvta.to.shared.u64 t, %1; cvt.u32.u64 %0, t; }" : "=r"(a) : "l"(p));
    return a;
}
#define LDSM_X4(r0, r1, r2, r3, a) \
    asm volatile("ldmatrix.sync.aligned.m8n8.x4.shared.b16 {%0,%1,%2,%3}, [%4];" \
                 : "=r"(r0), "=r"(r1), "=r"(r2), "=r"(r3) : "r"(a))
#define HMMA(d0, d1, d2, d3, a0, a1, a2, a3, b0, b1) \
    asm volatile("mma.sync.aligned.m16n8k16.row.col.f32.bf16.bf16.f32 " \
                 "{%0,%1,%2,%3}, {%4,%5,%6,%7}, {%8,%9}, {%0,%1,%2,%3};" \
                 : "+f"(d0), "+f"(d1), "+f"(d2), "+f"(d3) \
                 : "r"(a0), "r"(a1), "r"(a2), "r"(a3), "r"(b0), "r"(b1))

__device__ __forceinline__ void st_split_g(char* hi, char* lo, uint32_t a, float4 v) {
    __nv_bfloat16 hx = __float2bfloat16(v.x), hy = __float2bfloat16(v.y);
    __nv_bfloat16 hz = __float2bfloat16(v.z), hw = __float2bfloat16(v.w);
    __nv_bfloat16 lx = __float2bfloat16(v.x - __bfloat162float(hx));
    __nv_bfloat16 ly = __float2bfloat16(v.y - __bfloat162float(hy));
    __nv_bfloat16 lz = __float2bfloat16(v.z - __bfloat162float(hz));
    __nv_bfloat16 lw = __float2bfloat16(v.w - __bfloat162float(hw));
    uint2 h = make_uint2((uint32_t)__bfloat16_as_ushort(hx) | ((uint32_t)__bfloat16_as_ushort(hy) << 16),
                         (uint32_t)__bfloat16_as_ushort(hz) | ((uint32_t)__bfloat16_as_ushort(hw) << 16));
    uint2 l = make_uint2((uint32_t)__bfloat16_as_ushort(lx) | ((uint32_t)__bfloat16_as_ushort(ly) << 16),
                         (uint32_t)__bfloat16_as_ushort(lz) | ((uint32_t)__bfloat16_as_ushort(lw) << 16));
    *reinterpret_cast<uint2*>(hi + a) = h;
    *reinterpret_cast<uint2*>(lo + a) = l;
}

__device__ __forceinline__ constexpr int pidx(int j, int k) {
    return j * 8 - j * (j - 1) / 2 + (k - j - 1);
}

// ---------------- K1: one-barrier 256-example GEMM per CTA -------------------
// grid (ceil(N/256), 9), 256 thr
// smem: Whi 32K | Wlo 32K | 4 x (fhi 16K | flo 16K) = 192K
#define SM_WHI 0
#define SM_WLO 32768
#define SM_F(t) (65536 + (t) * 32768)       // hi at +0, lo at +16384
#define K1_SMEM 196608

__global__ void __launch_bounds__(256, 1)
k1_gemm(const float* __restrict__ F, const float* __restrict__ Wg, int N)
{
    extern __shared__ char smem[];
    const uint32_t sb = smem_u32(smem);
    const int tid  = threadIdx.x;
    const int lane = tid & 31;
    const int warp = tid >> 5;          // 0..7
    const int rg   = warp & 3;          // rows [16rg, 16rg+16) within a 64-tile
    const int cg   = warp >> 2;         // cols [64cg, 64cg+64)
    const int m    = blockIdx.y;
    const int n0   = blockIdx.x * 256;
    const float4* Fg4 = reinterpret_cast<const float4*>(F);
    const float4* Wg4 = reinterpret_cast<const float4*>(Wg);

    // ---- up-front: convert W_m and 4 f tiles into split-bf16 smem ----------
    #pragma unroll
    for (int it = 0; it < 16; ++it) {
        int s = tid + it * 256;            // 0..4095
        int row = s >> 5, q = s & 31;
        st_split_g(smem + SM_WHI, smem + SM_WLO, bswz(row, q),
                   Wg4[(size_t)m * 4096 + s]);
    }
    #pragma unroll
    for (int t = 0; t < 4; ++t) {
        #pragma unroll
        for (int it = 0; it < 8; ++it) {
            int s = tid + it * 256;        // 0..2047
            int row = s >> 5, q = s & 31;
            int n = n0 + 64 * t + row;
            float4 v = make_float4(0.f, 0.f, 0.f, 0.f);
            if (n < N) v = Fg4[((size_t)n * MM + m) * 32 + q];
            st_split_g(smem + SM_F(t), smem + SM_F(t) + 16384, bswz(row, q), v);
        }
    }
    __syncthreads();

    // ---- MMA phase: B loaded once per kk, reused across 4 tiles ------------
    const int a_row = 16 * rg + (lane & 15);
    const int a_ch  = lane >> 4;
    const int b_rlo = (lane & 7) + ((lane >> 4) << 3);
    const int b_ch  = (lane >> 3) & 1;

    float acc[4][8][4];
    #pragma unroll
    for (int t = 0; t < 4; ++t)
        #pragma unroll
        for (int q = 0; q < 8; ++q)
            #pragma unroll
            for (int c = 0; c < 4; ++c) acc[t][q][c] = 0.f;

    #pragma unroll
    for (int kk = 0; kk < 8; ++kk) {
        uint32_t bh[16], bl[16];
        #pragma unroll
        for (int p = 0; p < 4; ++p) {
            const int brow = 64 * cg + 16 * p + b_rlo;
            LDSM_X4(bh[4*p+0], bh[4*p+1], bh[4*p+2], bh[4*p+3],
                    lmaddr(sb + SM_WHI, brow, 2 * kk + b_ch));
            LDSM_X4(bl[4*p+0], bl[4*p+1], bl[4*p+2], bl[4*p+3],
                    lmaddr(sb + SM_WLO, brow, 2 * kk + b_ch));
        }
        #pragma unroll
        for (int t = 0; t < 4; ++t) {
            uint32_t ah0, ah1, ah2, ah3, al0, al1, al2, al3;
            LDSM_X4(ah0, ah1, ah2, ah3,
                    lmaddr(sb + SM_F(t), a_row, 2 * kk + a_ch));
            LDSM_X4(al0, al1, al2, al3,
                    lmaddr(sb + SM_F(t) + 16384, a_row, 2 * kk + a_ch));
            #pragma unroll
            for (int p = 0; p < 4; ++p) {
                const int q0 = 2 * p, q1 = 2 * p + 1;
                HMMA(acc[t][q0][0], acc[t][q0][1], acc[t][q0][2], acc[t][q0][3],
                     ah0, ah1, ah2, ah3, bh[4*p+0], bh[4*p+1]);
                HMMA(acc[t][q1][0], acc[t][q1][1], acc[t][q1][2], acc[t][q1][3],
                     ah0, ah1, ah2, ah3, bh[4*p+2], bh[4*p+3]);
                HMMA(acc[t][q0][0], acc[t][q0][1], acc[t][q0][2], acc[t][q0][3],
                     ah0, ah1, ah2, ah3, bl[4*p+0], bl[4*p+1]);
                HMMA(acc[t][q1][0], acc[t][q1][1], acc[t][q1][2], acc[t][q1][3],
                     ah0, ah1, ah2, ah3, bl[4*p+2], bl[4*p+3]);
                HMMA(acc[t][q0][0], acc[t][q0][1], acc[t][q0][2], acc[t][q0][3],
                     al0, al1, al2, al3, bh[4*p+0], bh[4*p+1]);
                HMMA(acc[t][q1][0], acc[t][q1][1], acc[t][q1][2], acc[t][q1][3],
                     al0, al1, al2, al3, bh[4*p+2], bh[4*p+3]);
            }
        }
    }

    // ---- epilogue: relu + store g -------------------------------------------
    const int r0l = 16 * rg + (lane >> 2);
    const int cb  = 64 * cg + (lane & 3) * 2;
    #pragma unroll
    for (int t = 0; t < 4; ++t) {
        const int r0 = n0 + 64 * t + r0l;
        #pragma unroll
        for (int q = 0; q < 8; ++q) {
            const int col = cb + 8 * q;
            if (r0 < N) {
                float2 v = make_float2(fmaxf(acc[t][q][0], 0.f), fmaxf(acc[t][q][1], 0.f));
                *reinterpret_cast<float2*>(g_g + ((size_t)r0 * MM + m) * DD + col) = v;
            }
            if (r0 + 8 < N) {
                float2 v = make_float2(fmaxf(acc[t][q][2], 0.f), fmaxf(acc[t][q][3], 0.f));
                *reinterpret_cast<float2*>(g_g + ((size_t)(r0 + 8) * MM + m) * DD + col) = v;
            }
        }
    }
}

// ---------------- K2: edges column-sum + fsum + output -----------------------
__global__ void __launch_bounds__(256)
k2_phase2(const float* __restrict__ F, float* __restrict__ out, int N)
{
    const int lane = threadIdx.x & 31;
    const int warp = threadIdx.x >> 5;
    const int n0   = blockIdx.x * 16;
    const float4* g4  = reinterpret_cast<const float4*>(g_g);
    const float4* Fg4 = reinterpret_cast<const float4*>(F);
    float4* out4 = reinterpret_cast<float4*>(out);

    #pragma unroll
    for (int ii = 0; ii < 2; ++ii) {
        const int n = n0 + warp * 2 + ii;
        if (n >= N) continue;

        float4 gm[MM];
        #pragma unroll
        for (int m = 0; m < MM; ++m)
            gm[m] = g4[((size_t)n * MM + m) * 32 + lane];

        float4 fs = Fg4[((size_t)n * MM) * 32 + lane];
        #pragma unroll
        for (int m = 1; m < MM; ++m) {
            float4 v = Fg4[((size_t)n * MM + m) * 32 + lane];
            fs.x += v.x; fs.y += v.y; fs.z += v.z; fs.w += v.w;
        }

        float mysA = 1.f, mysB = 1.f;
        #pragma unroll
        for (int j = 0; j < MM; ++j) {
            #pragma unroll
            for (int k = j + 1; k < MM; ++k) {
                const int p = pidx(j, k);
                float dx = gm[j].x - gm[k].x;
                float dy = gm[j].y - gm[k].y;
                float dz = gm[j].z - gm[k].z;
                float dw = gm[j].w - gm[k].w;
                float s = dx * dx;
                s = fmaf(dy, dy, s);
                s = fmaf(dz, dz, s);
                s = fmaf(dw, dw, s);
                s += __shfl_xor_sync(0xffffffffu, s, 16);
                s += __shfl_xor_sync(0xffffffffu, s, 8);
                s += __shfl_xor_sync(0xffffffffu, s, 4);
                s += __shfl_xor_sync(0xffffffffu, s, 2);
                s += __shfl_xor_sync(0xffffffffu, s, 1);
                if (p < 32) { if (lane == p)      mysA = s; }
                else        { if (lane == p - 32) mysB = s; }
            }
        }

        float xA = (mysA > 0.f) ? mysA * __frsqrt_rn(mysA) : 0.f;
        float xB = (mysB > 0.f) ? mysB * __frsqrt_rn(mysB) : 0.f;
        float eA = 1.f - __fdividef(2.f, __expf(2.f * xA) + 1.f);
        float eB = 1.f - __fdividef(2.f, __expf(2.f * xB) + 1.f);

        float cs[MM];
        #pragma unroll
        for (int k = 0; k < MM; ++k) {
            float a = 0.f;
            #pragma unroll
            for (int j = 0; j < MM; ++j) {
                if (j == k) continue;
                const int p = (j < k) ? pidx(j, k) : pidx(k, j);
                float e = (p < 32) ? __shfl_sync(0xffffffffu, eA, p)
                                   : __shfl_sync(0xffffffffu, eB, p - 32);
                a += e;
            }
            cs[k] = a;
        }

        float ux = 0.f, uy = 0.f, uz = 0.f, uw = 0.f;
        #pragma unroll
        for (int k = 0; k < MM; ++k) {
            ux = fmaf(cs[k], gm[k].x, ux);
            uy = fmaf(cs[k], gm[k].y, uy);
            uz = fmaf(cs[k], gm[k].z, uz);
            uw = fmaf(cs[k], gm[k].w, uw);
        }
        float4 o;
        o.x = 0.5f * (fs.x + ux);
        o.y = 0.5f * (fs.y + uy);
        o.z = 0.5f * (fs.z + uz);
        o.w = 0.5f * (fs.w + uw);
        out4[(size_t)n * 32 + lane] = o;
    }
}

// ----------------------------------------------------------------------------
extern "C" void kernel_launch(void* const* d_in, const int* in_sizes, int n_in,
                              void* d_out, int out_size) {
    const float* F = (const float*)d_in[0];   // [N,9,128] fp32
    const float* W = (const float*)d_in[1];   // [9,128,128] fp32
    float* out = (float*)d_out;               // [N,128] fp32
    const int N = in_sizes[0] / (MM * DD);

    cudaFuncSetAttribute(k1_gemm, cudaFuncAttributeMaxDynamicSharedMemorySize, K1_SMEM);

    dim3 g1((N + 255) / 256, MM);
    k1_gemm<<<g1, 256, K1_SMEM>>>(F, W, N);
    k2_phase2<<<(N + 15) / 16, 256>>>(F, out, N);
}

// round 10
// speedup vs baseline: 1.1016x; 1.1016x over previous
#include <cuda_runtime.h>
#include <cuda_bf16.h>
#include <cstdint>

#define MM 9
#define DD 128
#define NMAX 8192

// ---------------- global scratch (static, no dynamic alloc) ----------------
static __device__ __align__(128) float g_g[NMAX * MM * DD];

// ---------------- helpers ---------------------------------------------------
__device__ __forceinline__ uint32_t bswz(int row, int q) {
    int c = q >> 1;
    int cs = (c & 8) | ((c & 7) ^ (row & 7));
    return (uint32_t)(row * 256 + cs * 16 + (q & 1) * 8);
}
__device__ __forceinline__ uint32_t lmaddr(uint32_t base, int row, int chunk) {
    int cs = (chunk & 8) | ((chunk & 7) ^ (row & 7));
    return base + (uint32_t)(row * 256 + cs * 16);
}
__device__ __forceinline__ uint32_t smem_u32(const void* p) {
    uint32_t a;
    asm("{ .reg .u64 t; cvta.to.shared.u64 t, %1; cvt.u32.u64 %0, t; }" : "=r"(a) : "l"(p));
    return a;
}
#define LDSM_X4(r0, r1, r2, r3, a) \
    asm volatile("ldmatrix.sync.aligned.m8n8.x4.shared.b16 {%0,%1,%2,%3}, [%4];" \
                 : "=r"(r0), "=r"(r1), "=r"(r2), "=r"(r3) : "r"(a))
#define HMMA(d0, d1, d2, d3, a0, a1, a2, a3, b0, b1) \
    asm volatile("mma.sync.aligned.m16n8k16.row.col.f32.bf16.bf16.f32 " \
                 "{%0,%1,%2,%3}, {%4,%5,%6,%7}, {%8,%9}, {%0,%1,%2,%3};" \
                 : "+f"(d0), "+f"(d1), "+f"(d2), "+f"(d3) \
                 : "r"(a0), "r"(a1), "r"(a2), "r"(a3), "r"(b0), "r"(b1))

__device__ __forceinline__ void st_split_g(char* hi, char* lo, uint32_t a, float4 v) {
    __nv_bfloat16 hx = __float2bfloat16(v.x), hy = __float2bfloat16(v.y);
    __nv_bfloat16 hz = __float2bfloat16(v.z), hw = __float2bfloat16(v.w);
    __nv_bfloat16 lx = __float2bfloat16(v.x - __bfloat162float(hx));
    __nv_bfloat16 ly = __float2bfloat16(v.y - __bfloat162float(hy));
    __nv_bfloat16 lz = __float2bfloat16(v.z - __bfloat162float(hz));
    __nv_bfloat16 lw = __float2bfloat16(v.w - __bfloat162float(hw));
    uint2 h = make_uint2((uint32_t)__bfloat16_as_ushort(hx) | ((uint32_t)__bfloat16_as_ushort(hy) << 16),
                         (uint32_t)__bfloat16_as_ushort(hz) | ((uint32_t)__bfloat16_as_ushort(hw) << 16));
    uint2 l = make_uint2((uint32_t)__bfloat16_as_ushort(lx) | ((uint32_t)__bfloat16_as_ushort(ly) << 16),
                         (uint32_t)__bfloat16_as_ushort(lz) | ((uint32_t)__bfloat16_as_ushort(lw) << 16));
    *reinterpret_cast<uint2*>(hi + a) = h;
    *reinterpret_cast<uint2*>(lo + a) = l;
}

// ---------------- K1: persistent-W split-bf16 HMMA (R8, W conv inlined) ------
// grid (32, 9), 256 thr; smem: fhi 16K | flo 16K | Whi 32K | Wlo 32K = 96K
#define SM_FHI 0
#define SM_FLO 16384
#define SM_WHI 32768
#define SM_WLO 65536
#define K1_SMEM 98304
#define NTILE_STRIDE 32

__global__ void __launch_bounds__(256, 2)
k1_gemm(const float* __restrict__ F, const float* __restrict__ Wg, int N)
{
    extern __shared__ char smem[];
    const uint32_t sb = smem_u32(smem);
    const int tid  = threadIdx.x;
    const int lane = tid & 31;
    const int warp = tid >> 5;          // 0..7
    const int rg   = warp & 3;          // rows [16rg, 16rg+16)
    const int cg   = warp >> 2;         // cols [64cg, 64cg+64)
    const int m    = blockIdx.y;
    const int ntiles = (N + 63) / 64;
    const float4* Fg4 = reinterpret_cast<const float4*>(F);
    const float4* Wg4 = reinterpret_cast<const float4*>(Wg);

    // loader geometry: 8 float4 slots per thread
    int lrow[8], lq[8];
    #pragma unroll
    for (int it = 0; it < 8; ++it) {
        int s = tid + it * 256;          // 0..2047
        lrow[it] = s >> 5; lq[it] = s & 31;
    }

    // prefetch f for first tile (long-latency LDGs issued first)
    float4 fraw[8];
    {
        const int n0 = blockIdx.x * 64;
        #pragma unroll
        for (int it = 0; it < 8; ++it) {
            int n = n0 + lrow[it];
            fraw[it] = make_float4(0.f, 0.f, 0.f, 0.f);
            if (n < N) fraw[it] = Fg4[((size_t)n * MM + m) * 32 + lq[it]];
        }
    }

    // convert W_m (fp32, L2-resident) into split-bf16 smem, ONCE per CTA
    #pragma unroll
    for (int it = 0; it < 16; ++it) {
        int s = tid + it * 256;            // 0..4095
        int row = s >> 5, q = s & 31;
        st_split_g(smem + SM_WHI, smem + SM_WLO, bswz(row, q),
                   Wg4[(size_t)m * 4096 + s]);
    }
    __syncthreads();           // W resident

    const int a_row = 16 * rg + (lane & 15);
    const int a_ch  = lane >> 4;
    const int b_rlo = (lane & 7) + ((lane >> 4) << 3);
    const int b_ch  = (lane >> 3) & 1;

    for (int t = blockIdx.x; t < ntiles; t += NTILE_STRIDE) {
        const int n0 = t * 64;

        // convert current f tile into split smem
        #pragma unroll
        for (int it = 0; it < 8; ++it)
            st_split_g(smem + SM_FHI, smem + SM_FLO, bswz(lrow[it], lq[it]), fraw[it]);
        __syncthreads();

        // prefetch next tile's raw f (overlaps the MMA chain below)
        const int tn = t + NTILE_STRIDE;
        if (tn < ntiles) {
            const int nn0 = tn * 64;
            #pragma unroll
            for (int it = 0; it < 8; ++it) {
                int n = nn0 + lrow[it];
                fraw[it] = make_float4(0.f, 0.f, 0.f, 0.f);
                if (n < N) fraw[it] = Fg4[((size_t)n * MM + m) * 32 + lq[it]];
            }
        }

        float acc[8][4];
        #pragma unroll
        for (int q = 0; q < 8; ++q)
            #pragma unroll
            for (int c = 0; c < 4; ++c) acc[q][c] = 0.f;

        #pragma unroll
        for (int kk = 0; kk < 8; ++kk) {
            uint32_t ah0, ah1, ah2, ah3, al0, al1, al2, al3;
            LDSM_X4(ah0, ah1, ah2, ah3, lmaddr(sb + SM_FHI, a_row, 2 * kk + a_ch));
            LDSM_X4(al0, al1, al2, al3, lmaddr(sb + SM_FLO, a_row, 2 * kk + a_ch));
            #pragma unroll
            for (int p = 0; p < 4; ++p) {
                const int brow = 64 * cg + 16 * p + b_rlo;
                uint32_t b0, b1, b2, b3, c0, c1, c2, c3;
                LDSM_X4(b0, b1, b2, b3, lmaddr(sb + SM_WHI, brow, 2 * kk + b_ch));
                LDSM_X4(c0, c1, c2, c3, lmaddr(sb + SM_WLO, brow, 2 * kk + b_ch));
                const int t0 = 2 * p, t1 = 2 * p + 1;
                HMMA(acc[t0][0], acc[t0][1], acc[t0][2], acc[t0][3],
                     ah0, ah1, ah2, ah3, b0, b1);
                HMMA(acc[t1][0], acc[t1][1], acc[t1][2], acc[t1][3],
                     ah0, ah1, ah2, ah3, b2, b3);
                HMMA(acc[t0][0], acc[t0][1], acc[t0][2], acc[t0][3],
                     ah0, ah1, ah2, ah3, c0, c1);
                HMMA(acc[t1][0], acc[t1][1], acc[t1][2], acc[t1][3],
                     ah0, ah1, ah2, ah3, c2, c3);
                HMMA(acc[t0][0], acc[t0][1], acc[t0][2], acc[t0][3],
                     al0, al1, al2, al3, b0, b1);
                HMMA(acc[t1][0], acc[t1][1], acc[t1][2], acc[t1][3],
                     al0, al1, al2, al3, b2, b3);
            }
        }

        // relu + store g[n][m][col]
        const int r0 = n0 + 16 * rg + (lane >> 2);
        const int cb = 64 * cg + (lane & 3) * 2;
        #pragma unroll
        for (int q = 0; q < 8; ++q) {
            const int col = cb + 8 * q;
            if (r0 < N) {
                float2 v = make_float2(fmaxf(acc[q][0], 0.f), fmaxf(acc[q][1], 0.f));
                *reinterpret_cast<float2*>(g_g + ((size_t)r0 * MM + m) * DD + col) = v;
            }
            if (r0 + 8 < N) {
                float2 v = make_float2(fmaxf(acc[q][2], 0.f), fmaxf(acc[q][3], 0.f));
                *reinterpret_cast<float2*>(g_g + ((size_t)(r0 + 8) * MM + m) * DD + col) = v;
            }
        }
        __syncthreads();   // f smem consumed; safe to overwrite next iteration
    }
}

// ---------------- K2: 16-lanes-per-example phase 2 ---------------------------
// warp = 2 examples; lane sl = lane&15 owns dims [8sl, 8sl+8)
__global__ void __launch_bounds__(256)
k2_phase2(const float* __restrict__ F, float* __restrict__ out, int N)
{
    const int lane = threadIdx.x & 31;
    const int warp = threadIdx.x >> 5;
    const int ex   = lane >> 4;          // 0..1
    const int sl   = lane & 15;          // 0..15
    const int nr   = blockIdx.x * 16 + warp * 2 + ex;
    const int n    = (nr < N) ? nr : (N - 1);   // clamp: keep warp converged
    const float4* g4  = reinterpret_cast<const float4*>(g_g);
    const float4* Fg4 = reinterpret_cast<const float4*>(F);
    float4* out4 = reinterpret_cast<float4*>(out);

    // load g: 9 slots x 8 dims (2 float4 each)
    float4 gm[MM][2];
    #pragma unroll
    for (int m = 0; m < MM; ++m) {
        gm[m][0] = g4[((size_t)n * MM + m) * 32 + sl * 2 + 0];
        gm[m][1] = g4[((size_t)n * MM + m) * 32 + sl * 2 + 1];
    }
    // fsum over m (exact fp32)
    float4 fs0 = Fg4[((size_t)n * MM) * 32 + sl * 2 + 0];
    float4 fs1 = Fg4[((size_t)n * MM) * 32 + sl * 2 + 1];
    #pragma unroll
    for (int m = 1; m < MM; ++m) {
        float4 v0 = Fg4[((size_t)n * MM + m) * 32 + sl * 2 + 0];
        float4 v1 = Fg4[((size_t)n * MM + m) * 32 + sl * 2 + 1];
        fs0.x += v0.x; fs0.y += v0.y; fs0.z += v0.z; fs0.w += v0.w;
        fs1.x += v1.x; fs1.y += v1.y; fs1.z += v1.z; fs1.w += v1.w;
    }

    // pairwise distances: 4-step butterfly within 16-lane group,
    // edge computed on all lanes, column sums accumulated inline
    float cs[MM];
    #pragma unroll
    for (int k = 0; k < MM; ++k) cs[k] = 0.f;

    #pragma unroll
    for (int j = 0; j < MM; ++j) {
        #pragma unroll
        for (int k = j + 1; k < MM; ++k) {
            float dx = gm[j][0].x - gm[k][0].x;
            float dy = gm[j][0].y - gm[k][0].y;
            float dz = gm[j][0].z - gm[k][0].z;
            float dw = gm[j][0].w - gm[k][0].w;
            float s = dx * dx;
            s = fmaf(dy, dy, s);
            s = fmaf(dz, dz, s);
            s = fmaf(dw, dw, s);
            dx = gm[j][1].x - gm[k][1].x;
            dy = gm[j][1].y - gm[k][1].y;
            dz = gm[j][1].z - gm[k][1].z;
            dw = gm[j][1].w - gm[k][1].w;
            s = fmaf(dx, dx, s);
            s = fmaf(dy, dy, s);
            s = fmaf(dz, dz, s);
            s = fmaf(dw, dw, s);
            s += __shfl_xor_sync(0xffffffffu, s, 8);
            s += __shfl_xor_sync(0xffffffffu, s, 4);
            s += __shfl_xor_sync(0xffffffffu, s, 2);
            s += __shfl_xor_sync(0xffffffffu, s, 1);
            float x = (s > 0.f) ? s * __frsqrt_rn(s) : 0.f;
            float e = 1.f - __fdividef(2.f, __expf(2.f * x) + 1.f);
            cs[j] += e;
            cs[k] += e;
        }
    }

    // updates: u = sum_k cs[k] * g[k]
    float4 u0 = make_float4(0.f, 0.f, 0.f, 0.f);
    float4 u1 = make_float4(0.f, 0.f, 0.f, 0.f);
    #pragma unroll
    for (int k = 0; k < MM; ++k) {
        u0.x = fmaf(cs[k], gm[k][0].x, u0.x);
        u0.y = fmaf(cs[k], gm[k][0].y, u0.y);
        u0.z = fmaf(cs[k], gm[k][0].z, u0.z);
        u0.w = fmaf(cs[k], gm[k][0].w, u0.w);
        u1.x = fmaf(cs[k], gm[k][1].x, u1.x);
        u1.y = fmaf(cs[k], gm[k][1].y, u1.y);
        u1.z = fmaf(cs[k], gm[k][1].z, u1.z);
        u1.w = fmaf(cs[k], gm[k][1].w, u1.w);
    }

    if (nr < N) {
        float4 o0, o1;
        o0.x = 0.5f * (fs0.x + u0.x);
        o0.y = 0.5f * (fs0.y + u0.y);
        o0.z = 0.5f * (fs0.z + u0.z);
        o0.w = 0.5f * (fs0.w + u0.w);
        o1.x = 0.5f * (fs1.x + u1.x);
        o1.y = 0.5f * (fs1.y + u1.y);
        o1.z = 0.5f * (fs1.z + u1.z);
        o1.w = 0.5f * (fs1.w + u1.w);
        out4[(size_t)nr * 32 + sl * 2 + 0] = o0;
        out4[(size_t)nr * 32 + sl * 2 + 1] = o1;
    }
}

// ----------------------------------------------------------------------------
extern "C" void kernel_launch(void* const* d_in, const int* in_sizes, int n_in,
                              void* d_out, int out_size) {
    const float* F = (const float*)d_in[0];   // [N,9,128] fp32
    const float* W = (const float*)d_in[1];   // [9,128,128] fp32
    float* out = (float*)d_out;               // [N,128] fp32
    const int N = in_sizes[0] / (MM * DD);

    cudaFuncSetAttribute(k1_gemm, cudaFuncAttributeMaxDynamicSharedMemorySize, K1_SMEM);

    dim3 g1(NTILE_STRIDE, MM);
    k1_gemm<<<g1, 256, K1_SMEM>>>(F, W, N);
    k2_phase2<<<(N + 15) / 16, 256>>>(F, out, N);
}